// round 16
// baseline (speedup 1.0000x reference)
#include <cuda_runtime.h>
#include <cuda_fp16.h>
#include <cstdint>
#include <math.h>

// Problem constants
#define BB   2
#define SS   2048
#define HH   16
#define DD   128
#define HID  2048
#define MROWS 4096          // B*S
#define KDIM  2048
#define N1    6144          // 3*HID
#define N2    2048
#define SCALE 0.08838834764831843f

// Scratch (allocation-free: __device__ globals) — fp16
__device__ __half g_q[BB*HH*SS*DD];            // (b,h,s,d)   (pre-scaled by SCALE)
__device__ __half g_k[BB*HH*SS*DD];            // (b,h,s,d)
__device__ __half g_v[BB*HH*SS*DD];            // (b,h,s,d)
__device__ __half g_attn[(size_t)MROWS*HID];   // (b,s,hid)
__device__ __half g_xr[(size_t)MROWS*KDIM];
__device__ __half g_wq[(size_t)N1*KDIM];
__device__ __half g_wo[(size_t)N2*KDIM];

// ---------------------------------------------------------------------------
// Helpers
// ---------------------------------------------------------------------------
__device__ __forceinline__ void cp_async16(uint32_t dst, const void* src) {
    asm volatile("cp.async.cg.shared.global [%0], [%1], 16;" :: "r"(dst), "l"(src));
}
__device__ __forceinline__ uint32_t smem_u32(const void* p) {
    uint32_t a;
    asm("{ .reg .u64 t; cvta.to.shared.u64 t, %1; cvt.u32.u64 %0, t; }"
        : "=r"(a) : "l"(p));
    return a;
}
// D += A*B : m16n8k16 f16 (row.col), fp32 accumulate
__device__ __forceinline__ void mma_f16(float* d, const uint32_t* a, const uint32_t* b) {
    asm volatile(
        "mma.sync.aligned.m16n8k16.row.col.f32.f16.f16.f32 "
        "{%0,%1,%2,%3}, {%4,%5,%6,%7}, {%8,%9}, {%0,%1,%2,%3};"
        : "+f"(d[0]), "+f"(d[1]), "+f"(d[2]), "+f"(d[3])
        : "r"(a[0]), "r"(a[1]), "r"(a[2]), "r"(a[3]), "r"(b[0]), "r"(b[1]));
}
#define LDSM4(r0, r1, r2, r3, addr)                                            \
    asm volatile("ldmatrix.sync.aligned.m8n8.x4.shared.b16 {%0,%1,%2,%3}, [%4];" \
                 : "=r"(r0), "=r"(r1), "=r"(r2), "=r"(r3) : "r"(addr))
#define LDSM4T(r0, r1, r2, r3, addr)                                           \
    asm volatile("ldmatrix.sync.aligned.m8n8.x4.trans.shared.b16 {%0,%1,%2,%3}, [%4];" \
                 : "=r"(r0), "=r"(r1), "=r"(r2), "=r"(r3) : "r"(addr))

// ---------------------------------------------------------------------------
// Pre-round pass: x, w_qkv, w_o (fp32) -> fp16 copies.
// ---------------------------------------------------------------------------
#define NX  ((size_t)MROWS*KDIM)
#define NWQ ((size_t)N1*KDIM)
#define NWO ((size_t)N2*KDIM)
#define NTOT4 ((NX + NWQ + NWO) / 4)

__global__ __launch_bounds__(256) void preround_kernel(const float* __restrict__ x,
                                                       const float* __restrict__ wq,
                                                       const float* __restrict__ wo) {
    size_t i4 = (size_t)blockIdx.x * 256 + threadIdx.x;
    if (i4 >= NTOT4) return;
    size_t i = i4 * 4;
    const float* src;
    __half* dst;
    if (i < NX)            { src = x  + i;              dst = g_xr + i; }
    else if (i < NX + NWQ) { src = wq + (i - NX);       dst = g_wq + (i - NX); }
    else                   { src = wo + (i - NX - NWQ); dst = g_wo + (i - NX - NWQ); }
    float4 v = *(const float4*)src;
    __half2 h0 = __floats2half2_rn(v.x, v.y);
    __half2 h1 = __floats2half2_rn(v.z, v.w);
    uint2 u;
    u.x = *(uint32_t*)&h0;
    u.y = *(uint32_t*)&h1;
    *(uint2*)dst = u;
}

// ---------------------------------------------------------------------------
// fp16 mma.sync GEMM, 128 threads (4 warps 2m x 2n), CTA tile 64x128.
// ---------------------------------------------------------------------------
#define MT 64
#define NT 128
#define KCH 64
#define STRH 72
#define STG_HALVES (MT*STRH + NT*STRH)        // 13824 halves
#define GEMM_SMEM  (2 * STG_HALVES * 2)       // 55296 bytes
#define GNCHUNK (KDIM / KCH)

template<int MODE>
__global__ __launch_bounds__(128, 4) void mma_gemm(float* __restrict__ C) {
    extern __shared__ __half smh[];
    uint32_t sb = smem_u32(smh);
    int tid = threadIdx.x;
    int wid = tid >> 5;
    int lid = tid & 31;
    int g   = lid >> 2;
    int tq  = lid & 3;

    const __half* A = (MODE == 0) ? g_xr : g_attn;
    const __half* W = (MODE == 0) ? g_wq : g_wo;
    int m0 = blockIdx.y * MT;
    int n0 = blockIdx.x * NT;

    int wm = (wid & 1) * 32;
    int wn = (wid >> 1) * 64;

    int la  = lid & 15;
    int lk  = (lid >> 4) << 3;
    int lb  = (lid & 7) + ((lid & 16) ? 8 : 0);
    int lbk = (lid & 8) ? 8 : 0;

    uint32_t aoff0 = ((wm + la) * STRH + lk) * 2;
    uint32_t aoff1 = aoff0 + 16 * STRH * 2;
    uint32_t boff[4];
#pragma unroll
    for (int p = 0; p < 4; ++p)
        boff[p] = (uint32_t)(MT * STRH + (wn + p * 16 + lb) * STRH + lbk) * 2;

    float acc[2][8][4];
#pragma unroll
    for (int i = 0; i < 2; ++i)
#pragma unroll
        for (int j = 0; j < 8; ++j)
#pragma unroll
            for (int q = 0; q < 4; ++q) acc[i][j][q] = 0.f;

    auto load_stage = [&](int stg, int k0) {
        uint32_t abase = sb + stg * STG_HALVES * 2;
        uint32_t bbase = abase + MT * STRH * 2;
#pragma unroll
        for (int j = 0; j < 4; ++j) {
            int ci = tid + j * 128;
            int r = ci >> 3, kc = ci & 7;
            cp_async16(abase + (r * STRH + kc * 8) * 2,
                       A + (size_t)(m0 + r) * KDIM + k0 + kc * 8);
        }
#pragma unroll
        for (int j = 0; j < 8; ++j) {
            int ci = tid + j * 128;
            int r = ci >> 3, kc = ci & 7;
            cp_async16(bbase + (r * STRH + kc * 8) * 2,
                       W + (size_t)(n0 + r) * KDIM + k0 + kc * 8);
        }
    };

    load_stage(0, 0);
    asm volatile("cp.async.commit_group;" ::: "memory");

    for (int u = 0; u < GNCHUNK; ++u) {
        if (u + 1 < GNCHUNK) {
            load_stage((u + 1) & 1, (u + 1) * KCH);
            asm volatile("cp.async.commit_group;" ::: "memory");
            asm volatile("cp.async.wait_group 1;" ::: "memory");
        } else {
            asm volatile("cp.async.wait_group 0;" ::: "memory");
        }
        __syncthreads();

        uint32_t stgbase = sb + (u & 1) * STG_HALVES * 2;

#pragma unroll
        for (int ks = 0; ks < 4; ++ks) {
            uint32_t koff = ks * 32;
            uint32_t af[2][4], bf[8][2];
            LDSM4(af[0][0], af[0][1], af[0][2], af[0][3], stgbase + aoff0 + koff);
            LDSM4(af[1][0], af[1][1], af[1][2], af[1][3], stgbase + aoff1 + koff);
#pragma unroll
            for (int p = 0; p < 4; ++p) {
                uint32_t b0, b1, b2, b3;
                LDSM4(b0, b1, b2, b3, stgbase + boff[p] + koff);
                bf[2 * p][0] = b0;     bf[2 * p][1] = b1;
                bf[2 * p + 1][0] = b2; bf[2 * p + 1][1] = b3;
            }
#pragma unroll
            for (int im = 0; im < 2; ++im)
#pragma unroll
                for (int in_ = 0; in_ < 8; ++in_)
                    mma_f16(acc[im][in_], af[im], bf[in_]);
        }
        __syncthreads();
    }

#pragma unroll
    for (int im = 0; im < 2; ++im) {
#pragma unroll
        for (int half = 0; half < 2; ++half) {
            int m = m0 + wm + im * 16 + g + half * 8;
            if (MODE == 0) {
                int qkvi = n0 >> 11;
                int rem  = n0 & 2047;
                int h = rem >> 7;
                int b = m >> 11, s = m & 2047;
                __half* dst = (qkvi == 0) ? g_q : ((qkvi == 1) ? g_k : g_v);
                __half* row = dst + (((size_t)(b * HH + h)) * SS + s) * DD;
#pragma unroll
                for (int in_ = 0; in_ < 8; ++in_) {
                    int dcol = wn + in_ * 8 + tq * 2;
                    __half2 hv = __floats2half2_rn(acc[im][in_][half * 2 + 0],
                                                   acc[im][in_][half * 2 + 1]);
                    *(__half2*)(row + dcol) = hv;
                }
            } else {
                float* row = C + (size_t)m * N2 + n0;
#pragma unroll
                for (int in_ = 0; in_ < 8; ++in_) {
                    int dcol = wn + in_ * 8 + tq * 2;
                    float2 v;
                    v.x = acc[im][in_][half * 2 + 0];
                    v.y = acc[im][in_][half * 2 + 1];
                    *(float2*)(row + dcol) = v;
                }
            }
        }
    }
}

// ---------------------------------------------------------------------------
// RoPE in-place on g_q, g_k. Q additionally scaled by SCALE (folded out of
// the flash softmax: S = (SCALE*Q)·K^T).
// ---------------------------------------------------------------------------
__global__ __launch_bounds__(256) void rope_kernel() {
    int idx = blockIdx.x * 256 + threadIdx.x;
    int d   = idx & 63;
    int row = idx >> 6;
    int s   = row & (SS - 1);

    float inv = expf(-(float)d * 0.14391156831212787f);
    float ang = (float)s * inv;
    float c, sn;
    sincosf(ang, &sn, &c);

    size_t base = (size_t)row * DD;
    float q0 = __half2float(g_q[base + d]), q1 = __half2float(g_q[base + d + 64]);
    g_q[base + d]      = __float2half_rn((q0 * c - q1 * sn) * SCALE);
    g_q[base + d + 64] = __float2half_rn((q1 * c + q0 * sn) * SCALE);
    float k0 = __half2float(g_k[base + d]), k1 = __half2float(g_k[base + d + 64]);
    g_k[base + d]      = __float2half_rn(k0 * c - k1 * sn);
    g_k[base + d + 64] = __float2half_rn(k1 * c + k0 * sn);
}

// ---------------------------------------------------------------------------
// Flash attention v8 — register P; SCALE pre-folded into Q; softmax before
// V-sync; warp-vote rescale skip.
// 128 threads (4 warps), q-tile 64, k-tile 64.
// smem halves: Q[64][136] | K 2x[64][136] | V[64][136] = 69632 B -> 3 CTAs/SM.
// ---------------------------------------------------------------------------
#define QSTRH 136
#define VSTRH 136
#define FQ_H 0
#define FK_H (64*QSTRH)
#define FK_BUFH (64*QSTRH)
#define FV_H (FK_H + 2*FK_BUFH)
#define FL_H (FV_H + 64*VSTRH)
#define FL7_SMEM_BYTES (FL_H * 2)        // 69632

__global__ __launch_bounds__(128, 3) void flash_kernel() {
    extern __shared__ __half smh[];
    uint32_t sb = smem_u32(smh);

    int tid = threadIdx.x;
    int wid = tid >> 5;
    int lid = tid & 31;
    int g   = lid >> 2;
    int tq  = lid & 3;
    int wm  = wid * 16;

    int bh = blockIdx.y;
    int qt = 31 - (int)blockIdx.x;       // heavy tiles first
    int q0 = qt * 64;
    int ntiles = qt + 1;

    int la  = lid & 15;
    int lk  = (lid >> 4) << 3;
    int lb  = (lid & 7) + ((lid & 16) ? 8 : 0);
    int lbk = (lid & 8) ? 8 : 0;

    uint32_t qa_off  = sb + (uint32_t)(FQ_H + (wm + la) * QSTRH + lk) * 2;
    uint32_t kb_base = sb + (uint32_t)FK_H * 2 + (uint32_t)(lb * QSTRH + lbk) * 2;
    uint32_t vb_off  = sb + (uint32_t)(FV_H + (lid & 15) * VSTRH + ((lid & 16) ? 8 : 0)) * 2;

    const __half* Qg = g_q + (size_t)bh * (SS * DD);
    const __half* Kg = g_k + (size_t)bh * (SS * DD);
    const __half* Vg = g_v + (size_t)bh * (SS * DD);

    // prologue: Q (64 x 128 halves) + K tile 0
#pragma unroll
    for (int j = 0; j < 8; ++j) {
        int ci = tid + j * 128;
        int r = ci >> 4, kc = ci & 15;
        cp_async16(sb + (FQ_H + r * QSTRH + kc * 8) * 2,
                   Qg + (size_t)(q0 + r) * DD + kc * 8);
    }
#pragma unroll
    for (int j = 0; j < 8; ++j) {
        int ci = tid + j * 128;
        int r = ci >> 4, kc = ci & 15;
        cp_async16(sb + (FK_H + r * QSTRH + kc * 8) * 2,
                   Kg + (size_t)r * DD + kc * 8);
    }
    asm volatile("cp.async.commit_group;" ::: "memory");

    int r0 = q0 + wm + g;
    int r1 = r0 + 8;

    float mx0 = -1e30f, mx1 = -1e30f, l0 = 0.f, l1 = 0.f;
    float o[16][4];
#pragma unroll
    for (int f = 0; f < 16; ++f)
#pragma unroll
        for (int q = 0; q < 4; ++q) o[f][q] = 0.f;

    for (int jt = 0; jt < ntiles; ++jt) {
        int kbase = jt * 64;
        bool haveNext = (jt + 1 < ntiles);
        if (jt > 0) __syncthreads();     // V / K-buf reuse safe

        // prefetch V[jt] then K[jt+1]
#pragma unroll
        for (int j = 0; j < 8; ++j) {
            int ci = tid + j * 128;
            int r = ci >> 4, kc = ci & 15;
            cp_async16(sb + (FV_H + r * VSTRH + kc * 8) * 2,
                       Vg + (size_t)(kbase + r) * DD + kc * 8);
        }
        asm volatile("cp.async.commit_group;" ::: "memory");
        if (haveNext) {
            int nb = (jt + 1) & 1;
#pragma unroll
            for (int j = 0; j < 8; ++j) {
                int ci = tid + j * 128;
                int r = ci >> 4, kc = ci & 15;
                cp_async16(sb + (FK_H + nb * FK_BUFH + r * QSTRH + kc * 8) * 2,
                           Kg + (size_t)(kbase + 64 + r) * DD + kc * 8);
            }
            asm volatile("cp.async.commit_group;" ::: "memory");
            asm volatile("cp.async.wait_group 2;" ::: "memory");   // K[jt] ready
        } else {
            asm volatile("cp.async.wait_group 1;" ::: "memory");
        }
        __syncthreads();

        // ---- S = Q K^T : 8 k-steps of 16, 8 n-frags (Q pre-scaled)
        uint32_t kb = kb_base + ((jt & 1) ? FK_BUFH * 2 : 0);
        float s[8][4];
#pragma unroll
        for (int f = 0; f < 8; ++f)
#pragma unroll
            for (int q = 0; q < 4; ++q) s[f][q] = 0.f;

#pragma unroll
        for (int ks = 0; ks < 8; ++ks) {
            uint32_t koff = ks * 32;
            uint32_t af[4], bf[8][2];
            LDSM4(af[0], af[1], af[2], af[3], qa_off + koff);
#pragma unroll
            for (int p = 0; p < 4; ++p) {
                uint32_t b0, b1, b2, b3;
                LDSM4(b0, b1, b2, b3, kb + p * 16 * QSTRH * 2 + koff);
                bf[2 * p][0] = b0;     bf[2 * p][1] = b1;
                bf[2 * p + 1][0] = b2; bf[2 * p + 1][1] = b3;
            }
#pragma unroll
            for (int f = 0; f < 8; ++f)
                mma_f16(s[f], af, bf[f]);
        }

        // ---- online softmax (registers only; no barrier needed yet)
        bool diag = (jt == qt);
        float tm0 = -1e30f, tm1 = -1e30f;
        if (diag) {
#pragma unroll
            for (int f = 0; f < 8; ++f) {
                int c0 = kbase + f * 8 + 2 * tq, c1 = c0 + 1;
                if (c0 > r0) s[f][0] = -1e30f;
                if (c1 > r0) s[f][1] = -1e30f;
                if (c0 > r1) s[f][2] = -1e30f;
                if (c1 > r1) s[f][3] = -1e30f;
            }
        }
#pragma unroll
        for (int f = 0; f < 8; ++f) {
            tm0 = fmaxf(tm0, fmaxf(s[f][0], s[f][1]));
            tm1 = fmaxf(tm1, fmaxf(s[f][2], s[f][3]));
        }
        tm0 = fmaxf(tm0, __shfl_xor_sync(0xffffffffu, tm0, 1));
        tm0 = fmaxf(tm0, __shfl_xor_sync(0xffffffffu, tm0, 2));
        tm1 = fmaxf(tm1, __shfl_xor_sync(0xffffffffu, tm1, 1));
        tm1 = fmaxf(tm1, __shfl_xor_sync(0xffffffffu, tm1, 2));
        float mn0 = fmaxf(mx0, tm0), mn1 = fmaxf(mx1, tm1);

        uint32_t ph[8][2];
        float ps0 = 0.f, ps1 = 0.f;
#pragma unroll
        for (int f = 0; f < 8; ++f) {
            float p0 = __expf(s[f][0] - mn0);
            float p1 = __expf(s[f][1] - mn0);
            float p2 = __expf(s[f][2] - mn1);
            float p3 = __expf(s[f][3] - mn1);
            __half2 h01 = __floats2half2_rn(p0, p1);
            __half2 h23 = __floats2half2_rn(p2, p3);
            float2 f01 = __half22float2(h01);
            float2 f23 = __half22float2(h23);
            ps0 += f01.x + f01.y;
            ps1 += f23.x + f23.y;
            ph[f][0] = *(uint32_t*)&h01;
            ph[f][1] = *(uint32_t*)&h23;
        }
        ps0 += __shfl_xor_sync(0xffffffffu, ps0, 1);
        ps0 += __shfl_xor_sync(0xffffffffu, ps0, 2);
        ps1 += __shfl_xor_sync(0xffffffffu, ps1, 1);
        ps1 += __shfl_xor_sync(0xffffffffu, ps1, 2);

        // warp-vote rescale skip: if no lane's max advanced, all alphas == 1
        bool grew = (mn0 > mx0) | (mn1 > mx1);
        if (__any_sync(0xffffffffu, grew)) {
            float a0 = __expf(mx0 - mn0), a1 = __expf(mx1 - mn1);
            l0 = l0 * a0 + ps0;
            l1 = l1 * a1 + ps1;
#pragma unroll
            for (int f = 0; f < 16; ++f) {
                o[f][0] *= a0; o[f][1] *= a0;
                o[f][2] *= a1; o[f][3] *= a1;
            }
        } else {
            l0 += ps0;
            l1 += ps1;
        }
        mx0 = mn0; mx1 = mn1;

        // V[jt] ready + visible before PV
        if (haveNext) asm volatile("cp.async.wait_group 1;" ::: "memory");
        else          asm volatile("cp.async.wait_group 0;" ::: "memory");
        __syncthreads();

        // ---- O += P V : P from registers; V via ldmatrix.trans
#pragma unroll
        for (int ks = 0; ks < 4; ++ks) {
            uint32_t af[4];
            af[0] = ph[2 * ks][0];
            af[1] = ph[2 * ks][1];
            af[2] = ph[2 * ks + 1][0];
            af[3] = ph[2 * ks + 1][1];
            uint32_t vrow = vb_off + (uint32_t)(ks * 16 * VSTRH) * 2;
#pragma unroll
            for (int p = 0; p < 8; ++p) {
                uint32_t b0, b1, b2, b3;
                LDSM4T(b0, b1, b2, b3, vrow + p * 32);
                uint32_t bf0[2] = {b0, b1};
                uint32_t bf1[2] = {b2, b3};
                mma_f16(o[2 * p], af, bf0);
                mma_f16(o[2 * p + 1], af, bf1);
            }
        }
    }

    // epilogue -> g_attn (fp16)
    float i0 = 1.f / l0, i1 = 1.f / l1;
    int b = bh >> 4, h = bh & 15;
    __half* base0 = g_attn + ((size_t)(b * SS + r0)) * HID + h * DD;
    __half* base1 = g_attn + ((size_t)(b * SS + r1)) * HID + h * DD;
#pragma unroll
    for (int f = 0; f < 16; ++f) {
        int c = f * 8 + 2 * tq;
        *(__half2*)(base0 + c) = __floats2half2_rn(o[f][0] * i0, o[f][1] * i0);
        *(__half2*)(base1 + c) = __floats2half2_rn(o[f][2] * i1, o[f][3] * i1);
    }
}

// ---------------------------------------------------------------------------
extern "C" void kernel_launch(void* const* d_in, const int* in_sizes, int n_in,
                              void* d_out, int out_size) {
    const float* x     = (const float*)d_in[0];
    const float* w_qkv = (const float*)d_in[1];
    const float* w_o   = (const float*)d_in[2];
    float* out = (float*)d_out;

    cudaFuncSetAttribute(mma_gemm<0>, cudaFuncAttributeMaxDynamicSharedMemorySize,
                         GEMM_SMEM);
    cudaFuncSetAttribute(mma_gemm<1>, cudaFuncAttributeMaxDynamicSharedMemorySize,
                         GEMM_SMEM);
    cudaFuncSetAttribute(flash_kernel, cudaFuncAttributeMaxDynamicSharedMemorySize,
                         FL7_SMEM_BYTES);

    // 0. Convert GEMM inputs to fp16
    preround_kernel<<<(unsigned)((NTOT4 + 255) / 256), 256>>>(x, w_qkv, w_o);

    // 1. QKV projection -> g_q/g_k/g_v (b,h,s,d)
    dim3 g1(N1 / NT, MROWS / MT);
    mma_gemm<0><<<g1, 128, GEMM_SMEM>>>(nullptr);

    // 2. RoPE in-place on q,k (SCALE folded into q)
    rope_kernel<<<(BB * HH * SS * 64) / 256, 256>>>();

    // 3. Flash attention -> g_attn
    flash_kernel<<<dim3(SS / 64, BB * HH), 128, FL7_SMEM_BYTES>>>();

    // 4. Output projection -> d_out (fp32)
    dim3 g2(N2 / NT, MROWS / MT);
    mma_gemm<1><<<g2, 128, GEMM_SMEM>>>(out);
}